// round 7
// baseline (speedup 1.0000x reference)
#include <cuda_runtime.h>
#include <math.h>
#include <stdint.h>

typedef unsigned long long ull;

#define T_STEPS 1024
#define BATCH   64
#define IN_DIM  512
#define H_DIM   1024

#define NCTA         128
#define SCAN_THREADS 1024
#define NWARPS       32
#define COLS_PER_CTA 8          // 128 CTAs * 8 cols = 1024
#define KCHUNK       256        // k-chunk staged in smem per double-buffer slot
#define NCHUNKS      (H_DIM / KCHUNK)   // 4
#define KSLICE       8          // k per warp per chunk (32 warps * 8 = 256)
#define WPK_PITCH    1030       // ull pitch per column (bank-stagger)

// Transposed hidden state, double-buffered: g_ht[p][col*BATCH + row]
__device__ float g_ht[2][H_DIM * BATCH];
// Grid barrier: monotonic arrival counter + separately-polled epoch word
__device__ ull g_count = 0ULL;
__device__ ull g_epoch = 0ULL;

// ---------------------------------------------------------------------------
// packed f32x2 helpers (Blackwell sm_103a)
// ---------------------------------------------------------------------------
__device__ __forceinline__ ull pack2(float a, float b)
{
    ull r; asm("mov.b64 %0, {%1, %2};" : "=l"(r) : "f"(a), "f"(b)); return r;
}
__device__ __forceinline__ void unpack2(ull v, float& a, float& b)
{
    asm("mov.b64 {%0, %1}, %2;" : "=f"(a), "=f"(b) : "l"(v));
}
__device__ __forceinline__ void fma2(ull& acc, ull a, ull b)
{
    asm("fma.rn.f32x2 %0, %1, %2, %0;" : "+l"(acc) : "l"(a), "l"(b));
}
__device__ __forceinline__ ull add2(ull a, ull b)
{
    ull r; asm("add.rn.f32x2 %0, %1, %2;" : "=l"(r) : "l"(a), "l"(b)); return r;
}

// ---------------------------------------------------------------------------
// Kernel 1: xproj = x @ Wx + b  (out doubles as xproj buffer)
// M=65536, K=512, N=1024. BM=128, BN=64, BK=16; 256 threads; 8x4 microtile.
// B tile pre-packed (w,w) in smem -> inner k: 4 LDS.128 + 16 FFMA2, no ALU.
// Double-buffered smem, global loads reg-staged one tile ahead.
// ---------------------------------------------------------------------------
#define XBM 128
#define XBN 64
#define XBK 16
#define XKT (IN_DIM / XBK)      // 32 k-tiles

__global__ void __launch_bounds__(256, 2) xproj_kernel(
    const float* __restrict__ x,
    const float* __restrict__ W,     // full (IN+H, H); Wx = rows [0,512)
    const float* __restrict__ bias,
    float* __restrict__ out)
{
    __shared__ float As[2][XBK][XBM];    // 2 x 8 KB
    __shared__ ull   Bsp[2][XBK][XBN];   // 2 x 8 KB (packed (w,w))

    const int tid  = threadIdx.x;
    const int row0 = blockIdx.y * XBM;
    const int col0 = blockIdx.x * XBN;

    const int ty = tid >> 4;               // 0..15: rows ty*8..ty*8+7
    const int tx = tid & 15;               // 0..15: cols tx*4..tx*4+3

    // global load assignments
    const int lmA = tid >> 1;              // 0..127
    const int lkA = (tid & 1) << 3;        // 0 or 8
    const int lkB = tid >> 4;              // 0..15
    const int lnB = (tid & 15) << 2;       // 0..60

    const float* xg = x + (size_t)(row0 + lmA) * IN_DIM + lkA;
    const float* wg = W + (size_t)lkB * H_DIM + col0 + lnB;

    ull acc[4][4];                          // [row-pair][col]
#pragma unroll
    for (int i = 0; i < 4; ++i)
#pragma unroll
        for (int j = 0; j < 4; ++j) acc[i][j] = 0ULL;

    float4 avA, avB, bv;

    // preload tile 0
    avA = *(const float4*)(xg + 0);
    avB = *(const float4*)(xg + 4);
    bv  = *(const float4*)(wg);

    // store tile 0 to smem[0]
    {
#pragma unroll
        for (int i = 0; i < 4; ++i) {
            As[0][lkA + i][lmA]     = (&avA.x)[i];
            As[0][lkA + 4 + i][lmA] = (&avB.x)[i];
        }
        Bsp[0][lkB][lnB + 0] = pack2(bv.x, bv.x);
        Bsp[0][lkB][lnB + 1] = pack2(bv.y, bv.y);
        Bsp[0][lkB][lnB + 2] = pack2(bv.z, bv.z);
        Bsp[0][lkB][lnB + 3] = pack2(bv.w, bv.w);
    }
    __syncthreads();

    for (int kt = 0; kt < XKT; ++kt) {
        const int cur = kt & 1;
        // prefetch next tile into registers
        if (kt + 1 < XKT) {
            const float* xn = xg + (kt + 1) * XBK;
            avA = *(const float4*)(xn + 0);
            avB = *(const float4*)(xn + 4);
            bv  = *(const float4*)(wg + (size_t)(kt + 1) * XBK * H_DIM);
        }

        // compute current tile
#pragma unroll
        for (int k = 0; k < XBK; ++k) {
            ulonglong2 a0 = *(const ulonglong2*)&As[cur][k][ty << 3];       // rows 0-3
            ulonglong2 a1 = *(const ulonglong2*)&As[cur][k][(ty << 3) + 4]; // rows 4-7
            ulonglong2 b0 = *(const ulonglong2*)&Bsp[cur][k][tx << 2];      // cols 0,1
            ulonglong2 b1 = *(const ulonglong2*)&Bsp[cur][k][(tx << 2) + 2];// cols 2,3
            fma2(acc[0][0], a0.x, b0.x); fma2(acc[0][1], a0.x, b0.y);
            fma2(acc[0][2], a0.x, b1.x); fma2(acc[0][3], a0.x, b1.y);
            fma2(acc[1][0], a0.y, b0.x); fma2(acc[1][1], a0.y, b0.y);
            fma2(acc[1][2], a0.y, b1.x); fma2(acc[1][3], a0.y, b1.y);
            fma2(acc[2][0], a1.x, b0.x); fma2(acc[2][1], a1.x, b0.y);
            fma2(acc[2][2], a1.x, b1.x); fma2(acc[2][3], a1.x, b1.y);
            fma2(acc[3][0], a1.y, b0.x); fma2(acc[3][1], a1.y, b0.y);
            fma2(acc[3][2], a1.y, b1.x); fma2(acc[3][3], a1.y, b1.y);
        }
        __syncthreads();

        // store prefetched tile
        if (kt + 1 < XKT) {
            const int nxt = (kt + 1) & 1;
#pragma unroll
            for (int i = 0; i < 4; ++i) {
                As[nxt][lkA + i][lmA]     = (&avA.x)[i];
                As[nxt][lkA + 4 + i][lmA] = (&avB.x)[i];
            }
            Bsp[nxt][lkB][lnB + 0] = pack2(bv.x, bv.x);
            Bsp[nxt][lkB][lnB + 1] = pack2(bv.y, bv.y);
            Bsp[nxt][lkB][lnB + 2] = pack2(bv.z, bv.z);
            Bsp[nxt][lkB][lnB + 3] = pack2(bv.w, bv.w);
            __syncthreads();
        }
    }

    float4 bb = *(const float4*)(bias + col0 + (tx << 2));
#pragma unroll
    for (int rp = 0; rp < 4; ++rp) {
        float v0c[4], v1c[4];
#pragma unroll
        for (int j = 0; j < 4; ++j) unpack2(acc[rp][j], v0c[j], v1c[j]);
        float* o0 = out + (size_t)(row0 + (ty << 3) + rp * 2 + 0) * H_DIM + col0 + (tx << 2);
        float* o1 = out + (size_t)(row0 + (ty << 3) + rp * 2 + 1) * H_DIM + col0 + (tx << 2);
        *(float4*)o0 = make_float4(v0c[0] + bb.x, v0c[1] + bb.y, v0c[2] + bb.z, v0c[3] + bb.w);
        *(float4*)o1 = make_float4(v1c[0] + bb.x, v1c[1] + bb.y, v1c[2] + bb.z, v1c[3] + bb.w);
    }
}

// ---------------------------------------------------------------------------
// Scan kernel helpers
// ---------------------------------------------------------------------------
__device__ __forceinline__ void cp_async16(float* sdst, const float* gsrc)
{
    unsigned sa = (unsigned)__cvta_generic_to_shared(sdst);
    asm volatile("cp.async.cg.shared.global [%0], [%1], 16;\n" :: "r"(sa), "l"(gsrc));
}

__device__ __forceinline__ void stage_chunk(const float* gsrc, float* sdst, int tid)
{
    // KCHUNK*BATCH = 16384 floats = 4096 float4s; 1024 threads * 4 each
#pragma unroll
    for (int i = 0; i < 4; ++i) {
        int idx = tid + i * SCAN_THREADS;
        cp_async16(sdst + idx * 4, gsrc + idx * 4);
    }
}

// Counter+epoch barrier: RMWs on g_count never contend with the read-polls,
// which target only g_epoch.
__device__ __forceinline__ void grid_barrier()
{
    __syncthreads();
    if (threadIdx.x == 0) {
        __threadfence();
        ull old = atomicAdd(&g_count, 1ULL);
        ull target = (old / NCTA + 1ULL) * (ull)NCTA;
        if (old + 1ULL == target) {
            asm volatile("st.release.gpu.global.u64 [%0], %1;" :: "l"(&g_epoch), "l"(target));
        } else {
            ull cur;
            do {
                asm volatile("ld.acquire.gpu.global.u64 %0, [%1];" : "=l"(cur) : "l"(&g_epoch));
            } while (cur < target);
        }
    }
    __syncthreads();
}

// ---------------------------------------------------------------------------
// Kernel 2: persistent recurrent scan.
// 128 CTAs x 1024 threads (32 warps, 8/SMSP). CTA owns 8 output columns.
// Microtile: 4 rows x 4 cols per thread (lane = rg(0..15) + 16*cg(0..1)).
// Warp w handles k-subslice [w*8, w*8+8) of each 256-k chunk.
// Partials red[j][s][lane] (lane-contiguous); epilogue distributed over
// warps 0..3 (warp e owns within-group column j=e).
// ---------------------------------------------------------------------------
__global__ void __launch_bounds__(SCAN_THREADS) scan_kernel(
    const float* __restrict__ hinit,  // initial h (B,H)
    const float* __restrict__ W,      // Wh = rows [512, 1536)
    float* __restrict__ out)
{
    extern __shared__ float smem[];
    ull*   wpk   = (ull*)smem;                          // 8 x 1030 ull = 65920 B
    float* hbuf0 = smem + 2 * 8 * WPK_PITCH;            // [256][64] floats (64 KB)
    float* hbuf1 = hbuf0 + KCHUNK * BATCH;              // (64 KB)
    ulonglong2* red = (ulonglong2*)hbuf0;               // [4][32][32] ull2 = 64KB, reused

    const int tid  = threadIdx.x;
    const int wid  = tid >> 5;                // warp 0..31
    const int lane = tid & 31;
    const int rg   = lane & 15;               // rows rg*4..rg*4+3
    const int cg   = lane >> 4;               // cols cg*4..cg*4+3
    const int col0 = blockIdx.x * COLS_PER_CTA;
    const int c0   = cg * 4;
    const int r0   = rg * 4;

    // Prologue A: transpose my 8 columns of initial h into g_ht[0]
    if (tid < COLS_PER_CTA * BATCH) {
        int cc = tid >> 6;        // 0..7
        int r  = tid & 63;        // 0..63
        g_ht[0][(col0 + cc) * BATCH + r] = hinit[(size_t)r * H_DIM + col0 + cc];
    }

    // Prologue B: pre-pack resident Wh slice: wpk[cc][k] = (w, w)
    for (int i = tid; i < H_DIM * COLS_PER_CTA; i += SCAN_THREADS) {
        int cc = i >> 10;
        int k  = i & 1023;
        float w = W[(size_t)(IN_DIM + k) * H_DIM + col0 + cc];
        wpk[cc * WPK_PITCH + k] = pack2(w, w);
    }

    grid_barrier();   // all transposes visible before step-0 staging

    // per-thread weight row pointers (4 cols), k-base = warp subslice
    const ull* wp0 = wpk + (c0 + 0) * WPK_PITCH + wid * KSLICE;
    const ull* wp1 = wpk + (c0 + 1) * WPK_PITCH + wid * KSLICE;
    const ull* wp2 = wpk + (c0 + 2) * WPK_PITCH + wid * KSLICE;
    const ull* wp3 = wpk + (c0 + 3) * WPK_PITCH + wid * KSLICE;

    // epilogue thread's output column and row offsets (warps 0..3 only)
    const int  colE = col0 + c0 + wid;                  // valid when wid<4
    const size_t eo0 = (size_t)(r0 + 0) * H_DIM + colE;
    const size_t eo1 = (size_t)(r0 + 1) * H_DIM + colE;
    const size_t eo2 = (size_t)(r0 + 2) * H_DIM + colE;
    const size_t eo3 = (size_t)(r0 + 3) * H_DIM + colE;

    // prefetch xp for step 0 (epilogue warps)
    float xp0 = 0.f, xp1 = 0.f, xp2 = 0.f, xp3 = 0.f;
    if (wid < 4) {
        xp0 = out[eo0]; xp1 = out[eo1]; xp2 = out[eo2]; xp3 = out[eo3];
    }

    for (int t = 0; t < T_STEPS; ++t) {
        const float* gh  = g_ht[t & 1];
        float*       ghn = g_ht[(t + 1) & 1];
        float*       outt = out + (size_t)t * BATCH * H_DIM;

        ull acc[2][4];
#pragma unroll
        for (int j = 0; j < 4; ++j) { acc[0][j] = 0ULL; acc[1][j] = 0ULL; }

        // stage chunk 0
        stage_chunk(gh, hbuf0, tid);
        asm volatile("cp.async.commit_group;\n" ::: "memory");

#pragma unroll
        for (int kc = 0; kc < NCHUNKS; ++kc) {
            asm volatile("cp.async.wait_group 0;\n" ::: "memory");
            __syncthreads();
            if (kc + 1 < NCHUNKS) {
                float* nbuf = ((kc + 1) & 1) ? hbuf1 : hbuf0;
                stage_chunk(gh + (size_t)(kc + 1) * KCHUNK * BATCH, nbuf, tid);
                asm volatile("cp.async.commit_group;\n" ::: "memory");
            }

            const float* buf = (kc & 1) ? hbuf1 : hbuf0;
            const float* hb  = buf + wid * KSLICE * BATCH + r0;  // my subslice
            const int kb = kc * KCHUNK;
#pragma unroll
            for (int kk = 0; kk < KSLICE; kk += 2) {
                const float* hp = hb + kk * BATCH;
                ulonglong2 hA = *(const ulonglong2*)(hp);          // rows r0..r0+3, k
                ulonglong2 hB = *(const ulonglong2*)(hp + BATCH);  // k+1
                ulonglong2 w0 = *(const ulonglong2*)(wp0 + kb + kk);
                ulonglong2 w1 = *(const ulonglong2*)(wp1 + kb + kk);
                ulonglong2 w2 = *(const ulonglong2*)(wp2 + kb + kk);
                ulonglong2 w3 = *(const ulonglong2*)(wp3 + kb + kk);
                fma2(acc[0][0], hA.x, w0.x); fma2(acc[1][0], hA.y, w0.x);
                fma2(acc[0][1], hA.x, w1.x); fma2(acc[1][1], hA.y, w1.x);
                fma2(acc[0][2], hA.x, w2.x); fma2(acc[1][2], hA.y, w2.x);
                fma2(acc[0][3], hA.x, w3.x); fma2(acc[1][3], hA.y, w3.x);
                fma2(acc[0][0], hB.x, w0.y); fma2(acc[1][0], hB.y, w0.y);
                fma2(acc[0][1], hB.x, w1.y); fma2(acc[1][1], hB.y, w1.y);
                fma2(acc[0][2], hB.x, w2.y); fma2(acc[1][2], hB.y, w2.y);
                fma2(acc[0][3], hB.x, w3.y); fma2(acc[1][3], hB.y, w3.y);
            }
        }

        // store partials: red[j][s=wid][lane], lane-contiguous
#pragma unroll
        for (int j = 0; j < 4; ++j)
            red[(j * NWARPS + wid) * 32 + lane] = make_ulonglong2(acc[0][j], acc[1][j]);
        __syncthreads();

        // distributed epilogue: warp e reduces + writes column j=e
        if (wid < 4) {
            ull s01 = 0ULL, s23 = 0ULL;
#pragma unroll
            for (int s = 0; s < NWARPS; ++s) {
                ulonglong2 p = red[(wid * NWARPS + s) * 32 + lane];
                s01 = add2(s01, p.x);
                s23 = add2(s23, p.y);
            }
            float v0, v1, v2, v3;
            unpack2(s01, v0, v1);
            unpack2(s23, v2, v3);
            v0 = tanhf(v0 + xp0);
            v1 = tanhf(v1 + xp1);
            v2 = tanhf(v2 + xp2);
            v3 = tanhf(v3 + xp3);

            // hidden state to output history (column-scattered, small)
            outt[eo0] = v0;
            outt[eo1] = v1;
            outt[eo2] = v2;
            outt[eo3] = v3;

            // transposed copy for next step's staging (coalesced float4)
            *(float4*)&ghn[colE * BATCH + r0] = make_float4(v0, v1, v2, v3);

            // prefetch next step's xp; latency hides under the grid barrier
            if (t + 1 < T_STEPS) {
                const float* outn = outt + BATCH * H_DIM;
                xp0 = outn[eo0]; xp1 = outn[eo1]; xp2 = outn[eo2]; xp3 = outn[eo3];
            }
        }

        grid_barrier();
    }
}

// ---------------------------------------------------------------------------
extern "C" void kernel_launch(void* const* d_in, const int* in_sizes, int n_in,
                              void* d_out, int out_size)
{
    (void)in_sizes; (void)n_in; (void)out_size;
    const float* x = (const float*)d_in[0];
    const float* h = (const float*)d_in[1];
    const float* W = (const float*)d_in[2];
    const float* b = (const float*)d_in[3];
    float* out = (float*)d_out;

    // 1) xproj = x @ Wx + b  -> out
    dim3 grid_x(H_DIM / XBN, (T_STEPS * BATCH) / XBM);
    xproj_kernel<<<grid_x, 256>>>(x, W, b, out);

    // 2) persistent recurrent scan (includes h transpose prologue)
    const size_t smem_bytes = (2 * 8 * WPK_PITCH + 2 * KCHUNK * BATCH) * sizeof(float);
    static int smem_set = 0;
    if (!smem_set) {
        cudaFuncSetAttribute(scan_kernel, cudaFuncAttributeMaxDynamicSharedMemorySize,
                             (int)smem_bytes);
        smem_set = 1;
    }
    scan_kernel<<<NCTA, SCAN_THREADS, smem_bytes>>>(h, W, out);
}